// round 1
// baseline (speedup 1.0000x reference)
#include <cuda_runtime.h>
#include <cuda_bf16.h>
#include <cstddef>

// Problem constants
#define BATCH   16
#define CIN     256
#define HH      64
#define WW      64
#define HW      4096           // 64*64
#define OC_QKV  768
#define HEADS   64
#define ATT_CH  512
#define OC_OUT  256
#define K_PROJ  512

// ---------------------------------------------------------------------------
// Scratch (static device globals — no runtime allocation)
// ---------------------------------------------------------------------------
__device__ float g_qkv[(size_t)BATCH * OC_QKV * HW];   // 201 MB
__device__ float g_agg[(size_t)BATCH * OC_QKV * HW];   // 201 MB
__device__ float g_kv [(size_t)BATCH * HEADS * 72];    // tiny
__device__ float g_att[(size_t)BATCH * ATT_CH * HW];   // 134 MB

// ---------------------------------------------------------------------------
// Kernel 1/5: fp32 SGEMM  C[b] = A(MxK) * B[b](KxN), optional fused BN epilogue
// BM=BN=128, BK=8, 256 threads, 8x8 microtile per thread.
// M,N,K all divisible by tile sizes for both call sites (no bounds checks).
// ---------------------------------------------------------------------------
#define BM 128
#define BN 128
#define BKT 8

__global__ __launch_bounds__(256, 2)
void sgemm_bn(const float* __restrict__ A, const float* __restrict__ Bmat,
              float* __restrict__ C, int M, int N, int K,
              const float* __restrict__ gamma, const float* __restrict__ beta,
              const float* __restrict__ mean,  const float* __restrict__ var)
{
    const int b  = blockIdx.z;
    const float* Bp = Bmat + (size_t)b * K * N;
    float*       Cp = C    + (size_t)b * M * N;
    const int m0 = blockIdx.y * BM;
    const int n0 = blockIdx.x * BN;

    __shared__ float As[BKT][BM];
    __shared__ float Bs[BKT][BN];

    const int tid = threadIdx.x;
    const int ty = tid >> 4;        // 0..15
    const int tx = tid & 15;        // 0..15

    const int arow = tid >> 1;            // 0..127
    const int acol = (tid & 1) * 4;       // 0 or 4
    const int brow = tid >> 5;            // 0..7
    const int bcol = (tid & 31) * 4;      // 0..124

    float acc[8][8];
    #pragma unroll
    for (int i = 0; i < 8; i++)
        #pragma unroll
        for (int j = 0; j < 8; j++) acc[i][j] = 0.f;

    for (int k0 = 0; k0 < K; k0 += BKT) {
        float4 av = *(const float4*)(A + (size_t)(m0 + arow) * K + k0 + acol);
        As[acol + 0][arow] = av.x;
        As[acol + 1][arow] = av.y;
        As[acol + 2][arow] = av.z;
        As[acol + 3][arow] = av.w;
        *(float4*)&Bs[brow][bcol] =
            *(const float4*)(Bp + (size_t)(k0 + brow) * N + n0 + bcol);
        __syncthreads();

        #pragma unroll
        for (int k = 0; k < BKT; k++) {
            float a[8], bb[8];
            *(float4*)(a)      = *(const float4*)&As[k][ty * 8];
            *(float4*)(a + 4)  = *(const float4*)&As[k][ty * 8 + 4];
            *(float4*)(bb)     = *(const float4*)&Bs[k][tx * 8];
            *(float4*)(bb + 4) = *(const float4*)&Bs[k][tx * 8 + 4];
            #pragma unroll
            for (int i = 0; i < 8; i++)
                #pragma unroll
                for (int j = 0; j < 8; j++)
                    acc[i][j] += a[i] * bb[j];
        }
        __syncthreads();
    }

    #pragma unroll
    for (int i = 0; i < 8; i++) {
        const int m = m0 + ty * 8 + i;
        float scale = 1.f, shift = 0.f;
        if (gamma) {
            float inv = gamma[m] * rsqrtf(var[m] + 1e-5f);
            scale = inv;
            shift = beta[m] - mean[m] * inv;
        }
        float4 o0, o1;
        o0.x = acc[i][0] * scale + shift;
        o0.y = acc[i][1] * scale + shift;
        o0.z = acc[i][2] * scale + shift;
        o0.w = acc[i][3] * scale + shift;
        o1.x = acc[i][4] * scale + shift;
        o1.y = acc[i][5] * scale + shift;
        o1.z = acc[i][6] * scale + shift;
        o1.w = acc[i][7] * scale + shift;
        float* cr = Cp + (size_t)m * N + n0 + tx * 8;
        *(float4*)(cr)     = o0;
        *(float4*)(cr + 4) = o1;
    }
}

// ---------------------------------------------------------------------------
// Kernel 2: fused depthwise 3x3 (SAME, zero pad) + grouped 1x1 (8->8 per group)
// One block = (batch b, group g, 16-row strip). smem holds 8 channels w/ halo.
// ---------------------------------------------------------------------------
__global__ __launch_bounds__(256)
void dwpw_kernel(const float* __restrict__ qkv,
                 const float* __restrict__ wdw,   // [768][9]
                 const float* __restrict__ wpw,   // [768][8]
                 float* __restrict__ agg)
{
    const int strip = blockIdx.x;   // 0..3
    const int g     = blockIdx.y;   // 0..95
    const int b     = blockIdx.z;
    const int r0    = strip * 16;

    __shared__ float s_in[8][18][68];
    __shared__ float s_wdw[8][9];
    __shared__ float s_wpw[8][8];

    const int tid = threadIdx.x;
    const float* base = qkv + ((size_t)b * OC_QKV + g * 8) * HW;

    // load 8 channels x 18 rows (with y halo) x 64 cols; set x halo to 0
    for (int idx = tid; idx < 8 * 18 * 16; idx += 256) {
        const int seg = idx & 15;
        const int row = idx >> 4;
        const int rr  = row % 18;
        const int ch  = row / 18;
        const int y   = r0 + rr - 1;
        float4 v = make_float4(0.f, 0.f, 0.f, 0.f);
        if (y >= 0 && y < HH)
            v = *(const float4*)(base + (size_t)ch * HW + y * WW + seg * 4);
        float* d = &s_in[ch][rr][1 + seg * 4];
        d[0] = v.x; d[1] = v.y; d[2] = v.z; d[3] = v.w;
        if (seg == 0)  s_in[ch][rr][0]  = 0.f;
        if (seg == 15) s_in[ch][rr][65] = 0.f;
    }
    if (tid < 72)
        s_wdw[tid / 9][tid % 9] = wdw[(size_t)(g * 8 + tid / 9) * 9 + tid % 9];
    if (tid >= 128 && tid < 192) {
        int t = tid - 128;
        s_wpw[t >> 3][t & 7] = wpw[(size_t)(g * 8 + (t >> 3)) * 8 + (t & 7)];
    }
    __syncthreads();

    float* obase = agg + ((size_t)b * OC_QKV + g * 8) * HW + r0 * WW;
    for (int p = tid; p < 16 * WW; p += 256) {
        const int py = p >> 6;
        const int px = p & 63;
        float dwv[8];
        #pragma unroll
        for (int ic = 0; ic < 8; ic++) {
            float s = 0.f;
            #pragma unroll
            for (int ky = 0; ky < 3; ky++)
                #pragma unroll
                for (int kx = 0; kx < 3; kx++)
                    s += s_in[ic][py + ky][px + kx] * s_wdw[ic][ky * 3 + kx];
            dwv[ic] = s;
        }
        #pragma unroll
        for (int oc = 0; oc < 8; oc++) {
            float s = 0.f;
            #pragma unroll
            for (int ic = 0; ic < 8; ic++) s += s_wpw[oc][ic] * dwv[ic];
            obase[(size_t)oc * HW + p] = s;
        }
    }
}

// ---------------------------------------------------------------------------
// Kernel 3: kv[b,h,d,e] = sum_n relu(k[n,d]) * v[n,e]  (v[:,8] == 1)
// One block per (head, batch); channel source: head<32 -> qkv, else agg.
// ---------------------------------------------------------------------------
__global__ __launch_bounds__(256)
void kv_kernel(const float* __restrict__ qkv, const float* __restrict__ agg,
               float* __restrict__ kvout)
{
    const int h = blockIdx.x;
    const int b = blockIdx.y;
    const float* src = (h < 32) ? qkv : agg;
    const int ch0 = (h & 31) * 24;
    const float* base = src + ((size_t)b * OC_QKV + ch0) * HW;

    float acc[8][9];
    #pragma unroll
    for (int d = 0; d < 8; d++)
        #pragma unroll
        for (int e = 0; e < 9; e++) acc[d][e] = 0.f;

    for (int n = threadIdx.x; n < HW; n += 256) {
        float kk[8], vv[8];
        #pragma unroll
        for (int d = 0; d < 8; d++)
            kk[d] = fmaxf(base[(size_t)(8 + d) * HW + n], 0.f);
        #pragma unroll
        for (int e = 0; e < 8; e++)
            vv[e] = base[(size_t)(16 + e) * HW + n];
        #pragma unroll
        for (int d = 0; d < 8; d++) {
            #pragma unroll
            for (int e = 0; e < 8; e++) acc[d][e] += kk[d] * vv[e];
            acc[d][8] += kk[d];
        }
    }

    __shared__ float sred[8][72];
    const int lane = threadIdx.x & 31;
    const int warp = threadIdx.x >> 5;
    #pragma unroll
    for (int d = 0; d < 8; d++)
        #pragma unroll
        for (int e = 0; e < 9; e++) {
            float v = acc[d][e];
            #pragma unroll
            for (int o = 16; o > 0; o >>= 1)
                v += __shfl_down_sync(0xffffffffu, v, o);
            if (lane == 0) sred[warp][d * 9 + e] = v;
        }
    __syncthreads();
    if (threadIdx.x < 72) {
        float s = 0.f;
        #pragma unroll
        for (int w = 0; w < 8; w++) s += sred[w][threadIdx.x];
        kvout[((size_t)b * HEADS + h) * 72 + threadIdx.x] = s;
    }
}

// ---------------------------------------------------------------------------
// Kernel 4: out[n,e] = (sum_d relu(q[n,d]) * kv[d,e]) ; att = out[:,:8]/(out[:,8]+1e-15)
// Write layout: att[b][h*8+d][n]
// ---------------------------------------------------------------------------
__global__ __launch_bounds__(256)
void apply_kernel(const float* __restrict__ qkv, const float* __restrict__ agg,
                  const float* __restrict__ kvin, float* __restrict__ att)
{
    const int h = blockIdx.x;
    const int b = blockIdx.y;
    const float* src = (h < 32) ? qkv : agg;
    const int ch0 = (h & 31) * 24;
    const float* qb = src + ((size_t)b * OC_QKV + ch0) * HW;

    __shared__ float s_kv[72];
    if (threadIdx.x < 72)
        s_kv[threadIdx.x] = kvin[((size_t)b * HEADS + h) * 72 + threadIdx.x];
    __syncthreads();

    float* ob = att + ((size_t)b * ATT_CH + h * 8) * HW;
    for (int n = threadIdx.x; n < HW; n += 256) {
        float q[8];
        #pragma unroll
        for (int d = 0; d < 8; d++)
            q[d] = fmaxf(qb[(size_t)d * HW + n], 0.f);
        float num[9];
        #pragma unroll
        for (int e = 0; e < 9; e++) {
            float s = 0.f;
            #pragma unroll
            for (int d = 0; d < 8; d++) s += q[d] * s_kv[d * 9 + e];
            num[e] = s;
        }
        const float r = 1.0f / (num[8] + 1e-15f);
        #pragma unroll
        for (int d = 0; d < 8; d++)
            ob[(size_t)d * HW + n] = num[d] * r;
    }
}

// ---------------------------------------------------------------------------
// Launch
// ---------------------------------------------------------------------------
extern "C" void kernel_launch(void* const* d_in, const int* in_sizes, int n_in,
                              void* d_out, int out_size)
{
    const float* x      = (const float*)d_in[0];
    const float* w_qkv  = (const float*)d_in[1];
    const float* w_dw   = (const float*)d_in[2];
    const float* w_pw   = (const float*)d_in[3];
    const float* w_proj = (const float*)d_in[4];
    const float* gamma  = (const float*)d_in[5];
    const float* beta   = (const float*)d_in[6];
    const float* mean   = (const float*)d_in[7];
    const float* var    = (const float*)d_in[8];
    float* out = (float*)d_out;

    float *qkv_p, *agg_p, *kv_p, *att_p;
    cudaGetSymbolAddress((void**)&qkv_p, g_qkv);
    cudaGetSymbolAddress((void**)&agg_p, g_agg);
    cudaGetSymbolAddress((void**)&kv_p,  g_kv);
    cudaGetSymbolAddress((void**)&att_p, g_att);

    // 1) qkv = W_qkv * x  (per batch): M=768, N=4096, K=256
    {
        dim3 grid(HW / BN, OC_QKV / BM, BATCH);
        sgemm_bn<<<grid, 256>>>(w_qkv, x, qkv_p, OC_QKV, HW, CIN,
                                nullptr, nullptr, nullptr, nullptr);
    }
    // 2) depthwise 3x3 + grouped pointwise
    {
        dim3 grid(4, 96, BATCH);
        dwpw_kernel<<<grid, 256>>>(qkv_p, w_dw, w_pw, agg_p);
    }
    // 3) kv reduction
    {
        dim3 grid(HEADS, BATCH);
        kv_kernel<<<grid, 256>>>(qkv_p, agg_p, kv_p);
    }
    // 4) attention apply
    {
        dim3 grid(HEADS, BATCH);
        apply_kernel<<<grid, 256>>>(qkv_p, agg_p, kv_p, att_p);
    }
    // 5) y = W_proj * att + BN  (per batch): M=256, N=4096, K=512
    {
        dim3 grid(HW / BN, OC_OUT / BM, BATCH);
        sgemm_bn<<<grid, 256>>>(w_proj, att_p, out, OC_OUT, HW, K_PROJ,
                                gamma, beta, mean, var);
    }
}

// round 4
// speedup vs baseline: 1.0953x; 1.0953x over previous
#include <cuda_runtime.h>
#include <cstdint>
#include <cstddef>

// Problem constants
#define BATCH   16
#define CIN     256
#define HH      64
#define WW      64
#define HW      4096
#define OC_QKV  768
#define HEADS   64
#define ATT_CH  512
#define OC_OUT  256
#define K_PROJ  512

// ---------------------------------------------------------------------------
// Scratch
// ---------------------------------------------------------------------------
__device__ float g_qkv[(size_t)BATCH * OC_QKV * HW];     // [b][ch][n]
__device__ float g_agg[(size_t)BATCH * OC_QKV * HW];     // [b][ch][n]
__device__ float g_kv [(size_t)BATCH * HEADS * 72];
__device__ float g_att[(size_t)BATCH * HW * ATT_CH];     // transposed [b][n][c]
__device__ float g_xt [(size_t)BATCH * HW * CIN];        // x^T [b][n][k]

// ---------------------------------------------------------------------------
// Helpers
// ---------------------------------------------------------------------------
__device__ __forceinline__ float tf32r(float x) {
    float r;
    asm("cvt.rna.tf32.f32 %0, %1;" : "=f"(r) : "f"(x));
    return r;
}

__device__ __forceinline__ void mma_tf32(float* d, const uint32_t* a, const uint32_t* b) {
    asm volatile(
        "mma.sync.aligned.m16n8k8.row.col.f32.tf32.tf32.f32 "
        "{%0,%1,%2,%3}, {%4,%5,%6,%7}, {%8,%9}, {%0,%1,%2,%3};"
        : "+f"(d[0]), "+f"(d[1]), "+f"(d[2]), "+f"(d[3])
        : "r"(a[0]), "r"(a[1]), "r"(a[2]), "r"(a[3]), "r"(b[0]), "r"(b[1]));
}

// ---------------------------------------------------------------------------
// tf32 tensor-core GEMM (warp mma.sync), 3-term hi/lo split on BOTH operands:
//   A*B ~= Ah*Bh + Al*Bh + Ah*Bl   (error ~2^-23, fp32-grade)
// C[z][m][n] = sum_k A[m][k] * B[z][n][k]
//   A: [M,K] row-major (weights, shared over z)
//   B: [HW,K] row-major per batch  (K-major)
//   C: [M,HW] per batch.  Optional fused BN (per-m affine).
// Block tile 128x128, K-chunk 32, 8 warps each 32(M) x 64(N).
// ---------------------------------------------------------------------------
#define SPAD 36   // row pitch in floats: float4-aligned, conflict-free frags

__global__ __launch_bounds__(256)
void gemm_mma(const float* __restrict__ A, const float* __restrict__ B,
              float* __restrict__ C, int M, int K,
              const float* __restrict__ gamma, const float* __restrict__ beta,
              const float* __restrict__ mean,  const float* __restrict__ var)
{
    __shared__ float As[128][SPAD];
    __shared__ float Bs[128][SPAD];

    const int tid  = threadIdx.x;
    const int wid  = tid >> 5;
    const int lane = tid & 31;
    const int g    = lane >> 2;      // 0..7
    const int tig  = lane & 3;       // 0..3

    const int n0 = blockIdx.x * 128;
    const int m0 = blockIdx.y * 128;
    const int z  = blockIdx.z;

    const int wm = (wid & 3) * 32;   // warp M offset in tile
    const int wn = (wid >> 2) * 64;  // warp N offset in tile

    const float* Bb = B + (size_t)z * HW * K;
    float*       Cb = C + (size_t)z * M * HW;

    float acc[2][8][4];
    #pragma unroll
    for (int mt = 0; mt < 2; mt++)
        #pragma unroll
        for (int nt = 0; nt < 8; nt++)
            #pragma unroll
            for (int j = 0; j < 4; j++) acc[mt][nt][j] = 0.f;

    const int fr = tid >> 3;         // 0..31 : row handled by this thread
    const int fc = (tid & 7) * 4;    // 0,4,...,28 : k offset (float4)

    const int nchunks = K >> 5;
    for (int c = 0; c < nchunks; c++) {
        const int k0 = c << 5;
        // --- fill 128x32 tiles of A and B (each thread: 4 rows apart) ---
        #pragma unroll
        for (int it = 0; it < 4; it++) {
            const int r = fr + it * 32;
            *(float4*)&As[r][fc] = *(const float4*)(A  + (size_t)(m0 + r) * K + k0 + fc);
            *(float4*)&Bs[r][fc] = *(const float4*)(Bb + (size_t)(n0 + r) * K + k0 + fc);
        }
        __syncthreads();

        #pragma unroll
        for (int ks = 0; ks < 4; ks++) {
            const int kk = ks * 8;
            // B fragments hi/lo for 8 n-tiles
            uint32_t bh[8][2], bl[8][2];
            #pragma unroll
            for (int nt = 0; nt < 8; nt++) {
                const int n = wn + nt * 8 + g;
                float b0 = Bs[n][kk + tig];
                float b1 = Bs[n][kk + tig + 4];
                float h0 = tf32r(b0), h1 = tf32r(b1);
                bh[nt][0] = __float_as_uint(h0);
                bh[nt][1] = __float_as_uint(h1);
                bl[nt][0] = __float_as_uint(tf32r(b0 - h0));
                bl[nt][1] = __float_as_uint(tf32r(b1 - h1));
            }
            #pragma unroll
            for (int mt = 0; mt < 2; mt++) {
                const int mr = wm + mt * 16;
                float a0 = As[mr + g    ][kk + tig];
                float a1 = As[mr + 8 + g][kk + tig];
                float a2 = As[mr + g    ][kk + tig + 4];
                float a3 = As[mr + 8 + g][kk + tig + 4];
                float h0 = tf32r(a0), h1 = tf32r(a1), h2 = tf32r(a2), h3 = tf32r(a3);
                uint32_t ahi[4] = { __float_as_uint(h0), __float_as_uint(h1),
                                    __float_as_uint(h2), __float_as_uint(h3) };
                uint32_t alo[4] = { __float_as_uint(tf32r(a0 - h0)),
                                    __float_as_uint(tf32r(a1 - h1)),
                                    __float_as_uint(tf32r(a2 - h2)),
                                    __float_as_uint(tf32r(a3 - h3)) };
                #pragma unroll
                for (int nt = 0; nt < 8; nt++) {
                    mma_tf32(acc[mt][nt], alo, bh[nt]);   // Al*Bh
                    mma_tf32(acc[mt][nt], ahi, bl[nt]);   // Ah*Bl
                    mma_tf32(acc[mt][nt], ahi, bh[nt]);   // Ah*Bh
                }
            }
        }
        __syncthreads();
    }

    // --- epilogue ---
    #pragma unroll
    for (int mt = 0; mt < 2; mt++) {
        const int mA = m0 + wm + mt * 16 + g;
        const int mB = mA + 8;
        float sA = 1.f, hA = 0.f, sB = 1.f, hB = 0.f;
        if (gamma) {
            float invA = gamma[mA] * rsqrtf(var[mA] + 1e-5f);
            float invB = gamma[mB] * rsqrtf(var[mB] + 1e-5f);
            sA = invA; hA = beta[mA] - mean[mA] * invA;
            sB = invB; hB = beta[mB] - mean[mB] * invB;
        }
        float* rowA = Cb + (size_t)mA * HW + n0 + wn + 2 * tig;
        float* rowB = Cb + (size_t)mB * HW + n0 + wn + 2 * tig;
        #pragma unroll
        for (int nt = 0; nt < 8; nt++) {
            float2 oA, oB;
            oA.x = acc[mt][nt][0] * sA + hA;
            oA.y = acc[mt][nt][1] * sA + hA;
            oB.x = acc[mt][nt][2] * sB + hB;
            oB.y = acc[mt][nt][3] * sB + hB;
            *(float2*)(rowA + nt * 8) = oA;
            *(float2*)(rowB + nt * 8) = oB;
        }
    }
}

// ---------------------------------------------------------------------------
// Transpose x: [b][k=256][n=4096] -> xt [b][n][k]
// ---------------------------------------------------------------------------
__global__ __launch_bounds__(256)
void transpose_kernel(const float* __restrict__ in, float* __restrict__ out)
{
    __shared__ float t[32][33];
    const int b  = blockIdx.z;
    const int n0 = blockIdx.x * 32;
    const int k0 = blockIdx.y * 32;
    const int tx = threadIdx.x & 31;
    const int ty = threadIdx.x >> 5;   // 0..7

    const float* ib = in + (size_t)b * CIN * HW;
    float*       ob = out + (size_t)b * HW * CIN;

    #pragma unroll
    for (int i = 0; i < 4; i++) {
        const int k = k0 + ty + i * 8;
        t[ty + i * 8][tx] = ib[(size_t)k * HW + n0 + tx];
    }
    __syncthreads();
    #pragma unroll
    for (int i = 0; i < 4; i++) {
        const int n = n0 + ty + i * 8;
        ob[(size_t)n * CIN + k0 + tx] = t[tx][ty + i * 8];
    }
}

// ---------------------------------------------------------------------------
// Fused depthwise 3x3 + grouped 1x1
// ---------------------------------------------------------------------------
__global__ __launch_bounds__(256)
void dwpw_kernel(const float* __restrict__ qkv,
                 const float* __restrict__ wdw,
                 const float* __restrict__ wpw,
                 float* __restrict__ agg)
{
    const int strip = blockIdx.x;
    const int gg    = blockIdx.y;
    const int b     = blockIdx.z;
    const int r0    = strip * 16;

    __shared__ float s_in[8][18][68];
    __shared__ float s_wdw[8][9];
    __shared__ float s_wpw[8][8];

    const int tid = threadIdx.x;
    const float* base = qkv + ((size_t)b * OC_QKV + gg * 8) * HW;

    for (int idx = tid; idx < 8 * 18 * 16; idx += 256) {
        const int seg = idx & 15;
        const int row = idx >> 4;
        const int rr  = row % 18;
        const int ch  = row / 18;
        const int y   = r0 + rr - 1;
        float4 v = make_float4(0.f, 0.f, 0.f, 0.f);
        if (y >= 0 && y < HH)
            v = *(const float4*)(base + (size_t)ch * HW + y * WW + seg * 4);
        float* d = &s_in[ch][rr][1 + seg * 4];
        d[0] = v.x; d[1] = v.y; d[2] = v.z; d[3] = v.w;
        if (seg == 0)  s_in[ch][rr][0]  = 0.f;
        if (seg == 15) s_in[ch][rr][65] = 0.f;
    }
    if (tid < 72)
        s_wdw[tid / 9][tid % 9] = wdw[(size_t)(gg * 8 + tid / 9) * 9 + tid % 9];
    if (tid >= 128 && tid < 192) {
        int t = tid - 128;
        s_wpw[t >> 3][t & 7] = wpw[(size_t)(gg * 8 + (t >> 3)) * 8 + (t & 7)];
    }
    __syncthreads();

    float* obase = agg + ((size_t)b * OC_QKV + gg * 8) * HW + r0 * WW;
    for (int p = tid; p < 16 * WW; p += 256) {
        const int py = p >> 6;
        const int px = p & 63;
        float dwv[8];
        #pragma unroll
        for (int ic = 0; ic < 8; ic++) {
            float s = 0.f;
            #pragma unroll
            for (int ky = 0; ky < 3; ky++)
                #pragma unroll
                for (int kx = 0; kx < 3; kx++)
                    s += s_in[ic][py + ky][px + kx] * s_wdw[ic][ky * 3 + kx];
            dwv[ic] = s;
        }
        #pragma unroll
        for (int oc = 0; oc < 8; oc++) {
            float s = 0.f;
            #pragma unroll
            for (int ic = 0; ic < 8; ic++) s += s_wpw[oc][ic] * dwv[ic];
            obase[(size_t)oc * HW + p] = s;
        }
    }
}

// ---------------------------------------------------------------------------
// kv reduction
// ---------------------------------------------------------------------------
__global__ __launch_bounds__(256)
void kv_kernel(const float* __restrict__ qkv, const float* __restrict__ agg,
               float* __restrict__ kvout)
{
    const int h = blockIdx.x;
    const int b = blockIdx.y;
    const float* src = (h < 32) ? qkv : agg;
    const int ch0 = (h & 31) * 24;
    const float* base = src + ((size_t)b * OC_QKV + ch0) * HW;

    float acc[8][9];
    #pragma unroll
    for (int d = 0; d < 8; d++)
        #pragma unroll
        for (int e = 0; e < 9; e++) acc[d][e] = 0.f;

    for (int n = threadIdx.x; n < HW; n += 256) {
        float kk[8], vv[8];
        #pragma unroll
        for (int d = 0; d < 8; d++)
            kk[d] = fmaxf(base[(size_t)(8 + d) * HW + n], 0.f);
        #pragma unroll
        for (int e = 0; e < 8; e++)
            vv[e] = base[(size_t)(16 + e) * HW + n];
        #pragma unroll
        for (int d = 0; d < 8; d++) {
            #pragma unroll
            for (int e = 0; e < 8; e++) acc[d][e] += kk[d] * vv[e];
            acc[d][8] += kk[d];
        }
    }

    __shared__ float sred[8][72];
    const int lane = threadIdx.x & 31;
    const int warp = threadIdx.x >> 5;
    #pragma unroll
    for (int d = 0; d < 8; d++)
        #pragma unroll
        for (int e = 0; e < 9; e++) {
            float v = acc[d][e];
            #pragma unroll
            for (int o = 16; o > 0; o >>= 1)
                v += __shfl_down_sync(0xffffffffu, v, o);
            if (lane == 0) sred[warp][d * 9 + e] = v;
        }
    __syncthreads();
    if (threadIdx.x < 72) {
        float s = 0.f;
        #pragma unroll
        for (int w = 0; w < 8; w++) s += sred[w][threadIdx.x];
        kvout[((size_t)b * HEADS + h) * 72 + threadIdx.x] = s;
    }
}

// ---------------------------------------------------------------------------
// attention apply -> writes TRANSPOSED att [b][n][c] (K-major for GEMM2)
// ---------------------------------------------------------------------------
__global__ __launch_bounds__(256)
void apply_kernel(const float* __restrict__ qkv, const float* __restrict__ agg,
                  const float* __restrict__ kvin, float* __restrict__ att)
{
    const int h = blockIdx.x;
    const int b = blockIdx.y;
    const float* src = (h < 32) ? qkv : agg;
    const int ch0 = (h & 31) * 24;
    const float* qb = src + ((size_t)b * OC_QKV + ch0) * HW;

    __shared__ float s_kv[72];
    if (threadIdx.x < 72)
        s_kv[threadIdx.x] = kvin[((size_t)b * HEADS + h) * 72 + threadIdx.x];
    __syncthreads();

    float* ob = att + (size_t)b * HW * ATT_CH + h * 8;
    for (int n = threadIdx.x; n < HW; n += 256) {
        float q[8];
        #pragma unroll
        for (int d = 0; d < 8; d++)
            q[d] = fmaxf(qb[(size_t)d * HW + n], 0.f);
        float num[9];
        #pragma unroll
        for (int e = 0; e < 9; e++) {
            float s = 0.f;
            #pragma unroll
            for (int d = 0; d < 8; d++) s += q[d] * s_kv[d * 9 + e];
            num[e] = s;
        }
        const float r = 1.0f / (num[8] + 1e-15f);
        float4 o0, o1;
        o0.x = num[0] * r; o0.y = num[1] * r; o0.z = num[2] * r; o0.w = num[3] * r;
        o1.x = num[4] * r; o1.y = num[5] * r; o1.z = num[6] * r; o1.w = num[7] * r;
        float* dst = ob + (size_t)n * ATT_CH;
        *(float4*)(dst)     = o0;
        *(float4*)(dst + 4) = o1;
    }
}

// ---------------------------------------------------------------------------
// Launch
// ---------------------------------------------------------------------------
extern "C" void kernel_launch(void* const* d_in, const int* in_sizes, int n_in,
                              void* d_out, int out_size)
{
    const float* x      = (const float*)d_in[0];
    const float* w_qkv  = (const float*)d_in[1];
    const float* w_dw   = (const float*)d_in[2];
    const float* w_pw   = (const float*)d_in[3];
    const float* w_proj = (const float*)d_in[4];
    const float* gamma  = (const float*)d_in[5];
    const float* beta   = (const float*)d_in[6];
    const float* mean   = (const float*)d_in[7];
    const float* var    = (const float*)d_in[8];
    float* out = (float*)d_out;

    float *qkv_p, *agg_p, *kv_p, *att_p, *xt_p;
    cudaGetSymbolAddress((void**)&qkv_p, g_qkv);
    cudaGetSymbolAddress((void**)&agg_p, g_agg);
    cudaGetSymbolAddress((void**)&kv_p,  g_kv);
    cudaGetSymbolAddress((void**)&att_p, g_att);
    cudaGetSymbolAddress((void**)&xt_p,  g_xt);

    // 0) x^T
    {
        dim3 grid(HW / 32, CIN / 32, BATCH);
        transpose_kernel<<<grid, 256>>>(x, xt_p);
    }
    // 1) qkv = W_qkv * x : M=768, K=256
    {
        dim3 grid(HW / 128, OC_QKV / 128, BATCH);
        gemm_mma<<<grid, 256>>>(w_qkv, xt_p, qkv_p, OC_QKV, CIN,
                                nullptr, nullptr, nullptr, nullptr);
    }
    // 2) depthwise + grouped pointwise
    {
        dim3 grid(4, 96, BATCH);
        dwpw_kernel<<<grid, 256>>>(qkv_p, w_dw, w_pw, agg_p);
    }
    // 3) kv reduction
    {
        dim3 grid(HEADS, BATCH);
        kv_kernel<<<grid, 256>>>(qkv_p, agg_p, kv_p);
    }
    // 4) attention apply (writes transposed att)
    {
        dim3 grid(HEADS, BATCH);
        apply_kernel<<<grid, 256>>>(qkv_p, agg_p, kv_p, att_p);
    }
    // 5) y = W_proj * att + BN : M=256, K=512
    {
        dim3 grid(HW / 128, OC_OUT / 128, BATCH);
        gemm_mma<<<grid, 256>>>(w_proj, att_p, out, OC_OUT, K_PROJ,
                                gamma, beta, mean, var);
    }
}